// round 5
// baseline (speedup 1.0000x reference)
#include <cuda_runtime.h>
#include <cstdint>

#define NN 100000
#define EP 1000000
#define EN 500000

// ---------------- scratch (device globals: no allocations allowed) ----------
__device__ __align__(256) float g_aggA[NN * 64];   // pos-sourced aggregation sums
__device__ __align__(256) float g_aggB[NN * 64];   // neg-sourced aggregation sums
__device__ __align__(256) float g_z[NN * 64];      // layer1 output
__device__ __align__(256) float g_dpos[NN];        // sum of pos weights per dst
__device__ __align__(256) float g_dneg[NN];        // sum of neg weights per dst
// CSR build
__device__ __align__(256) int  g_pcnt[NN];
__device__ __align__(256) int  g_ncnt[NN];
__device__ __align__(256) int  g_poff[NN + 1];
__device__ __align__(256) int  g_noff[NN + 1];
__device__ __align__(256) int  g_pcur[NN];
__device__ __align__(256) int  g_ncur[NN];
__device__ __align__(256) int2 g_pedge[EP];        // (src, bitcast weight)
__device__ __align__(256) int2 g_nedge[EN];

// ---------------- helpers ----------------------------------------------------
__device__ __forceinline__ float tanha(float x) {
    float r;
    asm("tanh.approx.f32 %0, %1;" : "=f"(r) : "f"(x));
    return r;
}

// ---------------- CSR build --------------------------------------------------
__global__ void zero_cnt_kernel() {
    int i = blockIdx.x * blockDim.x + threadIdx.x;
    if (i < NN) {
        g_pcnt[i] = 0;
        g_ncnt[i] = 0;
        g_dpos[i] = 0.f;
        g_dneg[i] = 0.f;
    }
}

__global__ void hist_kernel(const int* __restrict__ pei, const int* __restrict__ nei,
                            const float* __restrict__ pw, const float* __restrict__ nw) {
    int t = blockIdx.x * blockDim.x + threadIdx.x;
    if (t < EP) {
        int d = pei[EP + t];
        atomicAdd(&g_pcnt[d], 1);
        atomicAdd(&g_dpos[d], pw[t]);
    } else if (t < EP + EN) {
        int e = t - EP;
        int d = nei[EN + e];
        atomicAdd(&g_ncnt[d], 1);
        atomicAdd(&g_dneg[d], nw[e]);
    }
}

// Single-block exclusive scan of both count arrays -> offsets + cursors.
__global__ void scan_kernel() {
    __shared__ int swsum[32];
    __shared__ int s_carry;
    int tid = threadIdx.x;
    int lane = tid & 31;
    int wid = tid >> 5;

#pragma unroll 1
    for (int pass = 0; pass < 2; pass++) {
        int* cnt = pass ? g_ncnt : g_pcnt;
        int* off = pass ? g_noff : g_poff;
        int* cur = pass ? g_ncur : g_pcur;
        if (tid == 0) s_carry = 0;
        __syncthreads();
#pragma unroll 1
        for (int base = 0; base < NN; base += 1024) {
            int i = base + tid;
            int v = (i < NN) ? cnt[i] : 0;
            int val = v;
#pragma unroll
            for (int o = 1; o < 32; o <<= 1) {
                int t2 = __shfl_up_sync(0xFFFFFFFFu, val, o);
                if (lane >= o) val += t2;
            }
            if (lane == 31) swsum[wid] = val;
            __syncthreads();
            if (wid == 0) {
                int s = swsum[lane];
#pragma unroll
                for (int o = 1; o < 32; o <<= 1) {
                    int t2 = __shfl_up_sync(0xFFFFFFFFu, s, o);
                    if (lane >= o) s += t2;
                }
                swsum[lane] = s;
            }
            __syncthreads();
            int woff = (wid > 0) ? swsum[wid - 1] : 0;
            int incl = val + woff;
            int c0 = s_carry;
            if (i < NN) {
                int e = c0 + incl - v;
                off[i] = e;
                cur[i] = e;
            }
            __syncthreads();
            if (tid == 1023) s_carry = c0 + incl;
            __syncthreads();
        }
        if (tid == 0) off[NN] = s_carry;
        __syncthreads();
    }
}

__global__ void fill_kernel(const int* __restrict__ pei, const int* __restrict__ nei,
                            const float* __restrict__ pw, const float* __restrict__ nw) {
    int t = blockIdx.x * blockDim.x + threadIdx.x;
    if (t < EP) {
        int src = pei[t];
        int dst = pei[EP + t];
        int slot = atomicAdd(&g_pcur[dst], 1);
        g_pedge[slot] = make_int2(src, __float_as_int(pw[t]));
    } else if (t < EP + EN) {
        int e = t - EP;
        int src = nei[e];
        int dst = nei[EN + e];
        int slot = atomicAdd(&g_ncur[dst], 1);
        g_nedge[slot] = make_int2(src, __float_as_int(nw[e]));
    }
}

// ---------------- CSR gather (both pos and neg in one pass) ------------------
// 16 threads per node; thread c owns float4 chunk c of the 64-float row.
// use_z: 0 -> feat = xfeat arg, 1 -> feat = g_z.
// swap: neg-side chunk c reads source chunk c^8 (layer-2 half swap).
__global__ void gather_kernel(const float4* __restrict__ xfeat, int use_z, int swap) {
    int t = blockIdx.x * blockDim.x + threadIdx.x;
    int n = t >> 4;
    if (n >= NN) return;
    int c = t & 15;
    const float4* feat = use_z ? reinterpret_cast<const float4*>(g_z) : xfeat;

    float4 accA = make_float4(0.f, 0.f, 0.f, 0.f);
    int b = g_poff[n], e = g_poff[n + 1];
#pragma unroll 2
    for (int i = b; i < e; i++) {
        int2 ed = g_pedge[i];
        float w = __int_as_float(ed.y);
        float4 v = feat[(size_t)ed.x * 16 + c];
        accA.x += w * v.x; accA.y += w * v.y; accA.z += w * v.z; accA.w += w * v.w;
    }

    int sc = c ^ (swap << 3);
    float4 accB = make_float4(0.f, 0.f, 0.f, 0.f);
    b = g_noff[n]; e = g_noff[n + 1];
#pragma unroll 2
    for (int i = b; i < e; i++) {
        int2 ed = g_nedge[i];
        float w = __int_as_float(ed.y);
        float4 v = feat[(size_t)ed.x * 16 + sc];
        accB.x += w * v.x; accB.y += w * v.y; accB.z += w * v.z; accB.w += w * v.w;
    }

    reinterpret_cast<float4*>(g_aggA)[n * 16 + c] = accA;
    reinterpret_cast<float4*>(g_aggB)[n * 16 + c] = accB;
}

// ---------------- layer 1: z = tanh([ap,x]@w1p+b1p | [an,x]@w1n+b1n) ---------
__global__ __launch_bounds__(128) void layer1_kernel(
    const float4* __restrict__ x4,
    const float* __restrict__ w1p, const float* __restrict__ b1p,
    const float* __restrict__ w1n, const float* __restrict__ b1n) {
    __shared__ float sWp[128 * 32];
    __shared__ float sWn[128 * 32];
    for (int i = threadIdx.x; i < 128 * 32; i += 128) {
        sWp[i] = w1p[i];
        sWn[i] = w1n[i];
    }
    __syncthreads();

    int n = blockIdx.x * 128 + threadIdx.x;
    if (n >= NN) return;

    float invp = 1.f / fmaxf(g_dpos[n], 1e-12f);
    float invn = 1.f / fmaxf(g_dneg[n], 1e-12f);

    float aP[32], aN[32];
#pragma unroll
    for (int j = 0; j < 32; j++) { aP[j] = b1p[j]; aN[j] = b1n[j]; }

    const float4* rA = reinterpret_cast<const float4*>(g_aggA) + n * 16;
    const float4* rB = reinterpret_cast<const float4*>(g_aggB) + n * 16;
    const float4* rX = x4 + n * 16;

#pragma unroll 1
    for (int k4 = 0; k4 < 16; k4++) {
        float4 a = rA[k4];
        float4 b = rB[k4];
        float4 xv = rX[k4];
        float av[4] = { a.x * invp, a.y * invp, a.z * invp, a.w * invp };
        float bv[4] = { b.x * invn, b.y * invn, b.z * invn, b.w * invn };
        float xe[4] = { xv.x, xv.y, xv.z, xv.w };
#pragma unroll
        for (int kk = 0; kk < 4; kk++) {
            int k = k4 * 4 + kk;
            const float4* wpA = reinterpret_cast<const float4*>(sWp + k * 32);
            const float4* wpX = reinterpret_cast<const float4*>(sWp + (64 + k) * 32);
            const float4* wnA = reinterpret_cast<const float4*>(sWn + k * 32);
            const float4* wnX = reinterpret_cast<const float4*>(sWn + (64 + k) * 32);
#pragma unroll
            for (int j4 = 0; j4 < 8; j4++) {
                float4 wp = wpA[j4];
                float4 wx = wpX[j4];
                float4 wn = wnA[j4];
                float4 wq = wnX[j4];
                aP[4 * j4 + 0] += av[kk] * wp.x + xe[kk] * wx.x;
                aP[4 * j4 + 1] += av[kk] * wp.y + xe[kk] * wx.y;
                aP[4 * j4 + 2] += av[kk] * wp.z + xe[kk] * wx.z;
                aP[4 * j4 + 3] += av[kk] * wp.w + xe[kk] * wx.w;
                aN[4 * j4 + 0] += bv[kk] * wn.x + xe[kk] * wq.x;
                aN[4 * j4 + 1] += bv[kk] * wn.y + xe[kk] * wq.y;
                aN[4 * j4 + 2] += bv[kk] * wn.z + xe[kk] * wq.z;
                aN[4 * j4 + 3] += bv[kk] * wn.w + xe[kk] * wq.w;
            }
        }
    }

    float4* zr = reinterpret_cast<float4*>(g_z + (size_t)n * 64);
#pragma unroll
    for (int j4 = 0; j4 < 8; j4++) {
        zr[j4] = make_float4(tanha(aP[4 * j4 + 0]), tanha(aP[4 * j4 + 1]),
                             tanha(aP[4 * j4 + 2]), tanha(aP[4 * j4 + 3]));
        zr[8 + j4] = make_float4(tanha(aN[4 * j4 + 0]), tanha(aN[4 * j4 + 1]),
                                 tanha(aN[4 * j4 + 2]), tanha(aN[4 * j4 + 3]));
    }
}

// ---------------- layer 2 ----------------------------------------------------
__global__ __launch_bounds__(128) void layer2_kernel(
    const float* __restrict__ w2p, const float* __restrict__ b2p,
    const float* __restrict__ w2n, const float* __restrict__ b2n) {
    __shared__ float sP[96 * 32];
    __shared__ float sN[96 * 32];
    for (int i = threadIdx.x; i < 96 * 32; i += 128) {
        sP[i] = w2p[i];
        sN[i] = w2n[i];
    }
    __syncthreads();

    int n = blockIdx.x * 128 + threadIdx.x;
    if (n >= NN) return;

    float invp = 1.f / fmaxf(g_dpos[n], 1e-12f);
    float invn = 1.f / fmaxf(g_dneg[n], 1e-12f);

    float aP[32], aN[32];
#pragma unroll
    for (int j = 0; j < 32; j++) { aP[j] = b2p[j]; aN[j] = b2n[j]; }

    const float4* rA = reinterpret_cast<const float4*>(g_aggA) + n * 16;
    const float4* rB = reinterpret_cast<const float4*>(g_aggB) + n * 16;
    const float4* rZ = reinterpret_cast<const float4*>(g_z) + n * 16;

#pragma unroll 1
    for (int k4 = 0; k4 < 8; k4++) {
        float4 A1 = rA[k4];
        float4 A3 = rA[8 + k4];
        float4 A2 = rB[k4];
        float4 A4 = rB[8 + k4];
        float4 zp = rZ[k4];
        float4 zn = rZ[8 + k4];
        float a1[4] = { A1.x * invp, A1.y * invp, A1.z * invp, A1.w * invp };
        float a3[4] = { A3.x * invp, A3.y * invp, A3.z * invp, A3.w * invp };
        float a2[4] = { A2.x * invn, A2.y * invn, A2.z * invn, A2.w * invn };
        float a4[4] = { A4.x * invn, A4.y * invn, A4.z * invn, A4.w * invn };
        float zpv[4] = { zp.x, zp.y, zp.z, zp.w };
        float znv[4] = { zn.x, zn.y, zn.z, zn.w };
#pragma unroll
        for (int kk = 0; kk < 4; kk++) {
            int k = k4 * 4 + kk;
            const float4* p0 = reinterpret_cast<const float4*>(sP + k * 32);
            const float4* p1 = reinterpret_cast<const float4*>(sP + (32 + k) * 32);
            const float4* p2 = reinterpret_cast<const float4*>(sP + (64 + k) * 32);
            const float4* q0 = reinterpret_cast<const float4*>(sN + k * 32);
            const float4* q1 = reinterpret_cast<const float4*>(sN + (32 + k) * 32);
            const float4* q2 = reinterpret_cast<const float4*>(sN + (64 + k) * 32);
#pragma unroll
            for (int j4 = 0; j4 < 8; j4++) {
                float4 w0 = p0[j4], w1 = p1[j4], w2 = p2[j4];
                aP[4 * j4 + 0] += a1[kk] * w0.x + a2[kk] * w1.x + zpv[kk] * w2.x;
                aP[4 * j4 + 1] += a1[kk] * w0.y + a2[kk] * w1.y + zpv[kk] * w2.y;
                aP[4 * j4 + 2] += a1[kk] * w0.z + a2[kk] * w1.z + zpv[kk] * w2.z;
                aP[4 * j4 + 3] += a1[kk] * w0.w + a2[kk] * w1.w + zpv[kk] * w2.w;
                float4 v0 = q0[j4], v1 = q1[j4], v2 = q2[j4];
                aN[4 * j4 + 0] += a3[kk] * v0.x + a4[kk] * v1.x + znv[kk] * v2.x;
                aN[4 * j4 + 1] += a3[kk] * v0.y + a4[kk] * v1.y + znv[kk] * v2.y;
                aN[4 * j4 + 2] += a3[kk] * v0.z + a4[kk] * v1.z + znv[kk] * v2.z;
                aN[4 * j4 + 3] += a3[kk] * v0.w + a4[kk] * v1.w + znv[kk] * v2.w;
            }
        }
    }

    float4* zr = reinterpret_cast<float4*>(g_z + (size_t)n * 64);
#pragma unroll
    for (int j4 = 0; j4 < 8; j4++) {
        zr[j4] = make_float4(tanha(aP[4 * j4 + 0]), tanha(aP[4 * j4 + 1]),
                             tanha(aP[4 * j4 + 2]), tanha(aP[4 * j4 + 3]));
        zr[8 + j4] = make_float4(tanha(aN[4 * j4 + 0]), tanha(aN[4 * j4 + 1]),
                                 tanha(aN[4 * j4 + 2]), tanha(aN[4 * j4 + 3]));
    }
}

// ---------------- layer 3: out = tanh(z2 @ wout + bout) ----------------------
__global__ __launch_bounds__(128) void layer3_kernel(
    const float* __restrict__ wout, const float* __restrict__ bout,
    float* __restrict__ out) {
    __shared__ float sO[64 * 64];
    for (int i = threadIdx.x; i < 64 * 64; i += 128) sO[i] = wout[i];
    __syncthreads();

    int n = blockIdx.x * 128 + threadIdx.x;
    if (n >= NN) return;

    float o[64];
#pragma unroll
    for (int j = 0; j < 64; j++) o[j] = bout[j];

    const float4* rz = reinterpret_cast<const float4*>(g_z) + n * 16;
#pragma unroll 1
    for (int k4 = 0; k4 < 16; k4++) {
        float4 zc = rz[k4];
        float zv[4] = { zc.x, zc.y, zc.z, zc.w };
#pragma unroll
        for (int kk = 0; kk < 4; kk++) {
            const float4* wr = reinterpret_cast<const float4*>(sO + (k4 * 4 + kk) * 64);
#pragma unroll
            for (int j4 = 0; j4 < 16; j4++) {
                float4 w = wr[j4];
                o[4 * j4 + 0] += zv[kk] * w.x;
                o[4 * j4 + 1] += zv[kk] * w.y;
                o[4 * j4 + 2] += zv[kk] * w.z;
                o[4 * j4 + 3] += zv[kk] * w.w;
            }
        }
    }

    float4* orow = reinterpret_cast<float4*>(out + (size_t)n * 64);
#pragma unroll
    for (int j4 = 0; j4 < 16; j4++) {
        orow[j4] = make_float4(tanha(o[4 * j4 + 0]), tanha(o[4 * j4 + 1]),
                               tanha(o[4 * j4 + 2]), tanha(o[4 * j4 + 3]));
    }
}

// ---------------- launch -----------------------------------------------------
extern "C" void kernel_launch(void* const* d_in, const int* in_sizes, int n_in,
                              void* d_out, int out_size) {
    const int*   pei  = (const int*)d_in[0];
    const int*   nei  = (const int*)d_in[1];
    const float* pw   = (const float*)d_in[2];
    const float* nw   = (const float*)d_in[3];
    const float* x    = (const float*)d_in[4];
    const float* w1p  = (const float*)d_in[5];
    const float* b1p  = (const float*)d_in[6];
    const float* w1n  = (const float*)d_in[7];
    const float* b1n  = (const float*)d_in[8];
    const float* w2p  = (const float*)d_in[9];
    const float* b2p  = (const float*)d_in[10];
    const float* w2n  = (const float*)d_in[11];
    const float* b2n  = (const float*)d_in[12];
    const float* wout = (const float*)d_in[13];
    const float* bout = (const float*)d_in[14];
    float* out = (float*)d_out;

    const int EB = (EP + EN + 255) / 256;
    const int GB = (NN * 16 + 255) / 256;
    const int LB = (NN + 127) / 128;

    // CSR build (shared by both layers)
    zero_cnt_kernel<<<(NN + 255) / 256, 256>>>();
    hist_kernel<<<EB, 256>>>(pei, nei, pw, nw);
    scan_kernel<<<1, 1024>>>();
    fill_kernel<<<EB, 256>>>(pei, nei, pw, nw);

    // Layer 1
    gather_kernel<<<GB, 256>>>((const float4*)x, 0, 0);
    layer1_kernel<<<LB, 128>>>((const float4*)x, w1p, b1p, w1n, b1n);

    // Layer 2 (neg side swaps zp/zn halves)
    gather_kernel<<<GB, 256>>>((const float4*)x, 1, 1);
    layer2_kernel<<<LB, 128>>>(w2p, b2p, w2n, b2n);
    layer3_kernel<<<LB, 128>>>(wout, bout, out);

    (void)in_sizes; (void)n_in; (void)out_size;
}

// round 6
// speedup vs baseline: 1.3506x; 1.3506x over previous
#include <cuda_runtime.h>
#include <cstdint>

#define NN 100000
#define EP 1000000
#define EN 500000
#define NBLK ((NN + 1023) / 1024)   // 98

// ---------------- scratch (device globals: no allocations allowed) ----------
__device__ __align__(256) float g_aggA[NN * 64];   // pos-sourced aggregation sums
__device__ __align__(256) float g_aggB[NN * 64];   // neg-sourced aggregation sums
__device__ __align__(256) float g_z[NN * 64];      // layer1 output, then layer2 output
__device__ __align__(256) float g_dpos[NN];        // sum of pos weights per dst
__device__ __align__(256) float g_dneg[NN];        // sum of neg weights per dst
// CSR build
__device__ __align__(256) int  g_pcnt[NN];
__device__ __align__(256) int  g_ncnt[NN];
__device__ __align__(256) int  g_poff[NN + 1];
__device__ __align__(256) int  g_noff[NN + 1];
__device__ __align__(256) int  g_prank[EP];
__device__ __align__(256) int  g_nrank[EN];
__device__ __align__(256) int  g_blksum[2][NBLK];
__device__ __align__(256) int  g_blkoff[2][NBLK];
__device__ __align__(256) int2 g_pedge[EP];        // (src, bitcast weight) in dst order
__device__ __align__(256) int2 g_nedge[EN];

// ---------------- helpers ----------------------------------------------------
__device__ __forceinline__ float tanha(float x) {
    float r;
    asm("tanh.approx.f32 %0, %1;" : "=f"(r) : "f"(x));
    return r;
}

// ---------------- CSR build --------------------------------------------------
__global__ void zero_cnt_kernel() {
    int i = blockIdx.x * blockDim.x + threadIdx.x;
    if (i < NN) {
        g_pcnt[i] = 0;
        g_ncnt[i] = 0;
        g_dpos[i] = 0.f;
        g_dneg[i] = 0.f;
    }
}

// Count edges per dst; the atomic's return value is this edge's rank within dst.
__global__ void hist_kernel(const int* __restrict__ pei, const int* __restrict__ nei,
                            const float* __restrict__ pw, const float* __restrict__ nw) {
    int t = blockIdx.x * blockDim.x + threadIdx.x;
    if (t < EP) {
        int d = pei[EP + t];
        g_prank[t] = atomicAdd(&g_pcnt[d], 1);
        atomicAdd(&g_dpos[d], pw[t]);
    } else if (t < EP + EN) {
        int e = t - EP;
        int d = nei[EN + e];
        g_nrank[e] = atomicAdd(&g_ncnt[d], 1);
        atomicAdd(&g_dneg[d], nw[e]);
    }
}

// Phase 1: per-block exclusive scan; block totals to g_blksum.
__global__ void scan1_kernel() {
    __shared__ int swsum[32];
    int arr = blockIdx.y;
    const int* cnt = arr ? g_ncnt : g_pcnt;
    int* off = arr ? g_noff : g_poff;
    int tid = threadIdx.x, lane = tid & 31, wid = tid >> 5;
    int i = blockIdx.x * 1024 + tid;
    int v = (i < NN) ? cnt[i] : 0;
    int val = v;
#pragma unroll
    for (int o = 1; o < 32; o <<= 1) {
        int t2 = __shfl_up_sync(0xFFFFFFFFu, val, o);
        if (lane >= o) val += t2;
    }
    if (lane == 31) swsum[wid] = val;
    __syncthreads();
    if (wid == 0) {
        int s = swsum[lane];
#pragma unroll
        for (int o = 1; o < 32; o <<= 1) {
            int t2 = __shfl_up_sync(0xFFFFFFFFu, s, o);
            if (lane >= o) s += t2;
        }
        swsum[lane] = s;
    }
    __syncthreads();
    int woff = wid ? swsum[wid - 1] : 0;
    int incl = val + woff;
    if (i < NN) off[i] = incl - v;
    if (tid == 1023) g_blksum[arr][blockIdx.x] = incl;
}

// Phase 2: scan the 98 block sums (one warp per array).
__global__ void scan2_kernel() {
    int lane = threadIdx.x & 31;
    int arr = threadIdx.x >> 5;
    if (arr >= 2) return;
    int carry = 0;
#pragma unroll 1
    for (int base = 0; base < NBLK; base += 32) {
        int idx = base + lane;
        int v = (idx < NBLK) ? g_blksum[arr][idx] : 0;
        int s = v;
#pragma unroll
        for (int o = 1; o < 32; o <<= 1) {
            int t2 = __shfl_up_sync(0xFFFFFFFFu, s, o);
            if (lane >= o) s += t2;
        }
        if (idx < NBLK) g_blkoff[arr][idx] = carry + s - v;
        carry += __shfl_sync(0xFFFFFFFFu, s, 31);
    }
    if (lane == 0) {
        if (arr) g_noff[NN] = carry;
        else     g_poff[NN] = carry;
    }
}

// Phase 3: add block offsets.
__global__ void scan3_kernel() {
    int arr = blockIdx.y;
    int* off = arr ? g_noff : g_poff;
    int i = blockIdx.x * 1024 + threadIdx.x;
    if (i < NN) off[i] += g_blkoff[arr][blockIdx.x];
}

// Fill CSR edge arrays — no atomics (slot = off[dst] + precomputed rank).
__global__ void fill_kernel(const int* __restrict__ pei, const int* __restrict__ nei,
                            const float* __restrict__ pw, const float* __restrict__ nw) {
    int t = blockIdx.x * blockDim.x + threadIdx.x;
    if (t < EP) {
        int dst = pei[EP + t];
        g_pedge[g_poff[dst] + g_prank[t]] = make_int2(pei[t], __float_as_int(pw[t]));
    } else if (t < EP + EN) {
        int e = t - EP;
        int dst = nei[EN + e];
        g_nedge[g_noff[dst] + g_nrank[e]] = make_int2(nei[e], __float_as_int(nw[e]));
    }
}

// ---------------- CSR gather (pos + neg in one pass, 4-deep pipelined) -------
// 16 threads per node; thread c owns float4 chunk c of the 64-float row.
__global__ void gather_kernel(const float4* __restrict__ xfeat, int use_z, int swap) {
    int t = blockIdx.x * blockDim.x + threadIdx.x;
    int n = t >> 4;
    if (n >= NN) return;
    int c = t & 15;
    const float4* feat = use_z ? reinterpret_cast<const float4*>(g_z) : xfeat;

    float4 accA = make_float4(0.f, 0.f, 0.f, 0.f);
    {
        int b = g_poff[n], e = g_poff[n + 1];
        int i = b;
        for (; i + 4 <= e; i += 4) {
            int2 e0 = g_pedge[i + 0];
            int2 e1 = g_pedge[i + 1];
            int2 e2 = g_pedge[i + 2];
            int2 e3 = g_pedge[i + 3];
            float4 v0 = __ldg(&feat[(size_t)e0.x * 16 + c]);
            float4 v1 = __ldg(&feat[(size_t)e1.x * 16 + c]);
            float4 v2 = __ldg(&feat[(size_t)e2.x * 16 + c]);
            float4 v3 = __ldg(&feat[(size_t)e3.x * 16 + c]);
            float w0 = __int_as_float(e0.y), w1 = __int_as_float(e1.y);
            float w2 = __int_as_float(e2.y), w3 = __int_as_float(e3.y);
            accA.x += w0 * v0.x + w1 * v1.x + w2 * v2.x + w3 * v3.x;
            accA.y += w0 * v0.y + w1 * v1.y + w2 * v2.y + w3 * v3.y;
            accA.z += w0 * v0.z + w1 * v1.z + w2 * v2.z + w3 * v3.z;
            accA.w += w0 * v0.w + w1 * v1.w + w2 * v2.w + w3 * v3.w;
        }
        for (; i < e; i++) {
            int2 ed = g_pedge[i];
            float w = __int_as_float(ed.y);
            float4 v = __ldg(&feat[(size_t)ed.x * 16 + c]);
            accA.x += w * v.x; accA.y += w * v.y; accA.z += w * v.z; accA.w += w * v.w;
        }
    }

    int sc = c ^ (swap << 3);
    float4 accB = make_float4(0.f, 0.f, 0.f, 0.f);
    {
        int b = g_noff[n], e = g_noff[n + 1];
        int i = b;
        for (; i + 4 <= e; i += 4) {
            int2 e0 = g_nedge[i + 0];
            int2 e1 = g_nedge[i + 1];
            int2 e2 = g_nedge[i + 2];
            int2 e3 = g_nedge[i + 3];
            float4 v0 = __ldg(&feat[(size_t)e0.x * 16 + sc]);
            float4 v1 = __ldg(&feat[(size_t)e1.x * 16 + sc]);
            float4 v2 = __ldg(&feat[(size_t)e2.x * 16 + sc]);
            float4 v3 = __ldg(&feat[(size_t)e3.x * 16 + sc]);
            float w0 = __int_as_float(e0.y), w1 = __int_as_float(e1.y);
            float w2 = __int_as_float(e2.y), w3 = __int_as_float(e3.y);
            accB.x += w0 * v0.x + w1 * v1.x + w2 * v2.x + w3 * v3.x;
            accB.y += w0 * v0.y + w1 * v1.y + w2 * v2.y + w3 * v3.y;
            accB.z += w0 * v0.z + w1 * v1.z + w2 * v2.z + w3 * v3.z;
            accB.w += w0 * v0.w + w1 * v1.w + w2 * v2.w + w3 * v3.w;
        }
        for (; i < e; i++) {
            int2 ed = g_nedge[i];
            float w = __int_as_float(ed.y);
            float4 v = __ldg(&feat[(size_t)ed.x * 16 + sc]);
            accB.x += w * v.x; accB.y += w * v.y; accB.z += w * v.z; accB.w += w * v.w;
        }
    }

    reinterpret_cast<float4*>(g_aggA)[n * 16 + c] = accA;
    reinterpret_cast<float4*>(g_aggB)[n * 16 + c] = accB;
}

// ---------------- layer 1: z = tanh([ap,x]@w1p+b1p | [an,x]@w1n+b1n) ---------
__global__ __launch_bounds__(128) void layer1_kernel(
    const float4* __restrict__ x4,
    const float* __restrict__ w1p, const float* __restrict__ b1p,
    const float* __restrict__ w1n, const float* __restrict__ b1n) {
    __shared__ float sWp[128 * 32];
    __shared__ float sWn[128 * 32];
    for (int i = threadIdx.x; i < 128 * 32; i += 128) {
        sWp[i] = w1p[i];
        sWn[i] = w1n[i];
    }
    __syncthreads();

    int n = blockIdx.x * 128 + threadIdx.x;
    if (n >= NN) return;

    float invp = 1.f / fmaxf(g_dpos[n], 1e-12f);
    float invn = 1.f / fmaxf(g_dneg[n], 1e-12f);

    float aP[32], aN[32];
#pragma unroll
    for (int j = 0; j < 32; j++) { aP[j] = b1p[j]; aN[j] = b1n[j]; }

    const float4* rA = reinterpret_cast<const float4*>(g_aggA) + n * 16;
    const float4* rB = reinterpret_cast<const float4*>(g_aggB) + n * 16;
    const float4* rX = x4 + n * 16;

#pragma unroll 1
    for (int k4 = 0; k4 < 16; k4++) {
        float4 a = rA[k4];
        float4 b = rB[k4];
        float4 xv = rX[k4];
        float av[4] = { a.x * invp, a.y * invp, a.z * invp, a.w * invp };
        float bv[4] = { b.x * invn, b.y * invn, b.z * invn, b.w * invn };
        float xe[4] = { xv.x, xv.y, xv.z, xv.w };
#pragma unroll
        for (int kk = 0; kk < 4; kk++) {
            int k = k4 * 4 + kk;
            const float4* wpA = reinterpret_cast<const float4*>(sWp + k * 32);
            const float4* wpX = reinterpret_cast<const float4*>(sWp + (64 + k) * 32);
            const float4* wnA = reinterpret_cast<const float4*>(sWn + k * 32);
            const float4* wnX = reinterpret_cast<const float4*>(sWn + (64 + k) * 32);
#pragma unroll
            for (int j4 = 0; j4 < 8; j4++) {
                float4 wp = wpA[j4];
                float4 wx = wpX[j4];
                float4 wn = wnA[j4];
                float4 wq = wnX[j4];
                aP[4 * j4 + 0] += av[kk] * wp.x + xe[kk] * wx.x;
                aP[4 * j4 + 1] += av[kk] * wp.y + xe[kk] * wx.y;
                aP[4 * j4 + 2] += av[kk] * wp.z + xe[kk] * wx.z;
                aP[4 * j4 + 3] += av[kk] * wp.w + xe[kk] * wx.w;
                aN[4 * j4 + 0] += bv[kk] * wn.x + xe[kk] * wq.x;
                aN[4 * j4 + 1] += bv[kk] * wn.y + xe[kk] * wq.y;
                aN[4 * j4 + 2] += bv[kk] * wn.z + xe[kk] * wq.z;
                aN[4 * j4 + 3] += bv[kk] * wn.w + xe[kk] * wq.w;
            }
        }
    }

    float4* zr = reinterpret_cast<float4*>(g_z + (size_t)n * 64);
#pragma unroll
    for (int j4 = 0; j4 < 8; j4++) {
        zr[j4] = make_float4(tanha(aP[4 * j4 + 0]), tanha(aP[4 * j4 + 1]),
                             tanha(aP[4 * j4 + 2]), tanha(aP[4 * j4 + 3]));
        zr[8 + j4] = make_float4(tanha(aN[4 * j4 + 0]), tanha(aN[4 * j4 + 1]),
                                 tanha(aN[4 * j4 + 2]), tanha(aN[4 * j4 + 3]));
    }
}

// ---------------- layer 2 ----------------------------------------------------
__global__ __launch_bounds__(128) void layer2_kernel(
    const float* __restrict__ w2p, const float* __restrict__ b2p,
    const float* __restrict__ w2n, const float* __restrict__ b2n) {
    __shared__ float sP[96 * 32];
    __shared__ float sN[96 * 32];
    for (int i = threadIdx.x; i < 96 * 32; i += 128) {
        sP[i] = w2p[i];
        sN[i] = w2n[i];
    }
    __syncthreads();

    int n = blockIdx.x * 128 + threadIdx.x;
    if (n >= NN) return;

    float invp = 1.f / fmaxf(g_dpos[n], 1e-12f);
    float invn = 1.f / fmaxf(g_dneg[n], 1e-12f);

    float aP[32], aN[32];
#pragma unroll
    for (int j = 0; j < 32; j++) { aP[j] = b2p[j]; aN[j] = b2n[j]; }

    const float4* rA = reinterpret_cast<const float4*>(g_aggA) + n * 16;
    const float4* rB = reinterpret_cast<const float4*>(g_aggB) + n * 16;
    const float4* rZ = reinterpret_cast<const float4*>(g_z) + n * 16;

#pragma unroll 1
    for (int k4 = 0; k4 < 8; k4++) {
        float4 A1 = rA[k4];
        float4 A3 = rA[8 + k4];
        float4 A2 = rB[k4];
        float4 A4 = rB[8 + k4];
        float4 zp = rZ[k4];
        float4 zn = rZ[8 + k4];
        float a1[4] = { A1.x * invp, A1.y * invp, A1.z * invp, A1.w * invp };
        float a3[4] = { A3.x * invp, A3.y * invp, A3.z * invp, A3.w * invp };
        float a2[4] = { A2.x * invn, A2.y * invn, A2.z * invn, A2.w * invn };
        float a4[4] = { A4.x * invn, A4.y * invn, A4.z * invn, A4.w * invn };
        float zpv[4] = { zp.x, zp.y, zp.z, zp.w };
        float znv[4] = { zn.x, zn.y, zn.z, zn.w };
#pragma unroll
        for (int kk = 0; kk < 4; kk++) {
            int k = k4 * 4 + kk;
            const float4* p0 = reinterpret_cast<const float4*>(sP + k * 32);
            const float4* p1 = reinterpret_cast<const float4*>(sP + (32 + k) * 32);
            const float4* p2 = reinterpret_cast<const float4*>(sP + (64 + k) * 32);
            const float4* q0 = reinterpret_cast<const float4*>(sN + k * 32);
            const float4* q1 = reinterpret_cast<const float4*>(sN + (32 + k) * 32);
            const float4* q2 = reinterpret_cast<const float4*>(sN + (64 + k) * 32);
#pragma unroll
            for (int j4 = 0; j4 < 8; j4++) {
                float4 w0 = p0[j4], w1 = p1[j4], w2 = p2[j4];
                aP[4 * j4 + 0] += a1[kk] * w0.x + a2[kk] * w1.x + zpv[kk] * w2.x;
                aP[4 * j4 + 1] += a1[kk] * w0.y + a2[kk] * w1.y + zpv[kk] * w2.y;
                aP[4 * j4 + 2] += a1[kk] * w0.z + a2[kk] * w1.z + zpv[kk] * w2.z;
                aP[4 * j4 + 3] += a1[kk] * w0.w + a2[kk] * w1.w + zpv[kk] * w2.w;
                float4 v0 = q0[j4], v1 = q1[j4], v2 = q2[j4];
                aN[4 * j4 + 0] += a3[kk] * v0.x + a4[kk] * v1.x + znv[kk] * v2.x;
                aN[4 * j4 + 1] += a3[kk] * v0.y + a4[kk] * v1.y + znv[kk] * v2.y;
                aN[4 * j4 + 2] += a3[kk] * v0.z + a4[kk] * v1.z + znv[kk] * v2.z;
                aN[4 * j4 + 3] += a3[kk] * v0.w + a4[kk] * v1.w + znv[kk] * v2.w;
            }
        }
    }

    float4* zr = reinterpret_cast<float4*>(g_z + (size_t)n * 64);
#pragma unroll
    for (int j4 = 0; j4 < 8; j4++) {
        zr[j4] = make_float4(tanha(aP[4 * j4 + 0]), tanha(aP[4 * j4 + 1]),
                             tanha(aP[4 * j4 + 2]), tanha(aP[4 * j4 + 3]));
        zr[8 + j4] = make_float4(tanha(aN[4 * j4 + 0]), tanha(aN[4 * j4 + 1]),
                                 tanha(aN[4 * j4 + 2]), tanha(aN[4 * j4 + 3]));
    }
}

// ---------------- layer 3: out = tanh(z2 @ wout + bout) ----------------------
__global__ __launch_bounds__(128) void layer3_kernel(
    const float* __restrict__ wout, const float* __restrict__ bout,
    float* __restrict__ out) {
    __shared__ float sO[64 * 64];
    for (int i = threadIdx.x; i < 64 * 64; i += 128) sO[i] = wout[i];
    __syncthreads();

    int n = blockIdx.x * 128 + threadIdx.x;
    if (n >= NN) return;

    float o[64];
#pragma unroll
    for (int j = 0; j < 64; j++) o[j] = bout[j];

    const float4* rz = reinterpret_cast<const float4*>(g_z) + n * 16;
#pragma unroll 1
    for (int k4 = 0; k4 < 16; k4++) {
        float4 zc = rz[k4];
        float zv[4] = { zc.x, zc.y, zc.z, zc.w };
#pragma unroll
        for (int kk = 0; kk < 4; kk++) {
            const float4* wr = reinterpret_cast<const float4*>(sO + (k4 * 4 + kk) * 64);
#pragma unroll
            for (int j4 = 0; j4 < 16; j4++) {
                float4 w = wr[j4];
                o[4 * j4 + 0] += zv[kk] * w.x;
                o[4 * j4 + 1] += zv[kk] * w.y;
                o[4 * j4 + 2] += zv[kk] * w.z;
                o[4 * j4 + 3] += zv[kk] * w.w;
            }
        }
    }

    float4* orow = reinterpret_cast<float4*>(out + (size_t)n * 64);
#pragma unroll
    for (int j4 = 0; j4 < 16; j4++) {
        orow[j4] = make_float4(tanha(o[4 * j4 + 0]), tanha(o[4 * j4 + 1]),
                               tanha(o[4 * j4 + 2]), tanha(o[4 * j4 + 3]));
    }
}

// ---------------- launch -----------------------------------------------------
extern "C" void kernel_launch(void* const* d_in, const int* in_sizes, int n_in,
                              void* d_out, int out_size) {
    const int*   pei  = (const int*)d_in[0];
    const int*   nei  = (const int*)d_in[1];
    const float* pw   = (const float*)d_in[2];
    const float* nw   = (const float*)d_in[3];
    const float* x    = (const float*)d_in[4];
    const float* w1p  = (const float*)d_in[5];
    const float* b1p  = (const float*)d_in[6];
    const float* w1n  = (const float*)d_in[7];
    const float* b1n  = (const float*)d_in[8];
    const float* w2p  = (const float*)d_in[9];
    const float* b2p  = (const float*)d_in[10];
    const float* w2n  = (const float*)d_in[11];
    const float* b2n  = (const float*)d_in[12];
    const float* wout = (const float*)d_in[13];
    const float* bout = (const float*)d_in[14];
    float* out = (float*)d_out;

    const int EB = (EP + EN + 255) / 256;
    const int GB = (NN * 16 + 255) / 256;
    const int LB = (NN + 127) / 128;

    // CSR build (shared by both layers)
    zero_cnt_kernel<<<(NN + 255) / 256, 256>>>();
    hist_kernel<<<EB, 256>>>(pei, nei, pw, nw);
    scan1_kernel<<<dim3(NBLK, 2), 1024>>>();
    scan2_kernel<<<1, 64>>>();
    scan3_kernel<<<dim3(NBLK, 2), 1024>>>();
    fill_kernel<<<EB, 256>>>(pei, nei, pw, nw);

    // Layer 1
    gather_kernel<<<GB, 256>>>((const float4*)x, 0, 0);
    layer1_kernel<<<LB, 128>>>((const float4*)x, w1p, b1p, w1n, b1n);

    // Layer 2 (neg side swaps zp/zn halves)
    gather_kernel<<<GB, 256>>>((const float4*)x, 1, 1);
    layer2_kernel<<<LB, 128>>>(w2p, b2p, w2n, b2n);
    layer3_kernel<<<LB, 128>>>(wout, bout, out);

    (void)in_sizes; (void)n_in; (void)out_size;
}